// round 11
// baseline (speedup 1.0000x reference)
#include <cuda_runtime.h>
#include <math.h>

#define SCALE 64.0f
#define MARGIN 0.35f
#define TPB 256
#define GROUPS 4            // float4 groups per thread -> 16 elements/thread
#define TILE (TPB * GROUPS * 4)   // 4096 output elements per block

// Output layout (f32, flattened tuple in reference order):
//   [0, B*(C-1))            diff_logits, row-major
//   [B*(C-1), +B)           sin_theta
//   [+B, +2B)               sin_theta_plus_m
//   [+2B, +3B)              sin_m
//
// Labels dtype sniff: for LE int64 labels in [0, 100000) every odd 32-bit
// word is 0; for int32 labels those words are random. 8 odd words decide.
__device__ __forceinline__ bool labels_are_i64(const int* labels32) {
    bool is_i64 = true;
#pragma unroll
    for (int k = 1; k <= 15; k += 2) is_i64 &= (labels32[k] == 0);
    return is_i64;
}

__global__ void cosface_kernel(const float* __restrict__ logits,
                               const int* __restrict__ labels32,
                               float* __restrict__ out,
                               int B, int C) {
    const int Cm1 = C - 1;
    const bool i64 = labels_are_i64(labels32);
    const int total = B * Cm1;
    const int total4 = total >> 2;

    const int tb = blockIdx.x * TILE;
    const int r0 = tb / Cm1;                       // one division per block
    const int base0 = r0 * Cm1;
    const int b1 = base0 + Cm1;
    const int lab0 = i64 ? labels32[2 * r0] : labels32[r0];
    const size_t lbase0 = (size_t)r0 * (size_t)C;
    const float ft0 = __ldg(logits + lbase0 + lab0) - MARGIN;

    const int j0 = tb - base0;                     // block's first j in row r0
    const int jend = j0 + TILE;
    float4* __restrict__ out4 = reinterpret_cast<float4*>(out);

    const bool uniform = (tb + TILE <= b1) && (tb + TILE <= total) &&
                         (lab0 <= j0 || lab0 >= jend);

    if (uniform) {
        // FAST PATH (~68% of blocks): single row, constant column shift.
        // Loads are base+immediate (zero per-element ALU); stores aligned st.128.
        const int shift = (j0 >= lab0) ? 1 : 0;
        const float* __restrict__ p = logits + lbase0 + j0 + shift;
        float4* __restrict__ o4 = out4 + (tb >> 2);

        float v[GROUPS][4];
#pragma unroll
        for (int g = 0; g < GROUPS; g++) {
            const int e0 = (threadIdx.x + g * TPB) << 2;
#pragma unroll
            for (int e = 0; e < 4; e++) v[g][e] = __ldcs(p + e0 + e);
        }
#pragma unroll
        for (int g = 0; g < GROUPS; g++) {
            float4 o;
            o.x = SCALE * (v[g][0] - ft0);
            o.y = SCALE * (v[g][1] - ft0);
            o.z = SCALE * (v[g][2] - ft0);
            o.w = SCALE * (v[g][3] - ft0);
            __stcs(o4 + threadIdx.x + g * TPB, o);
        }
    } else {
        // SLOW PATH: block contains the label and/or crosses a row boundary.
        const int r1 = (r0 + 1 < B) ? r0 + 1 : r0;
        const int lab1 = i64 ? labels32[2 * r1] : labels32[r1];
        const size_t lbase1 = (size_t)r1 * (size_t)C;
        const float ft1 = __ldg(logits + lbase1 + lab1) - MARGIN;

        int idx4[GROUPS];
        bool ok[GROUPS];
        float v[GROUPS][4];
#pragma unroll
        for (int g = 0; g < GROUPS; g++) {
            idx4[g] = (tb >> 2) + threadIdx.x + g * TPB;
            ok[g] = (idx4[g] < total4);
            if (ok[g]) {
                const int t0 = idx4[g] << 2;
#pragma unroll
                for (int e = 0; e < 4; e++) {
                    const int t = t0 + e;
                    const bool hi = (t >= b1);
                    const int j = t - (hi ? b1 : base0);
                    const int lab = hi ? lab1 : lab0;
                    const size_t src = (hi ? lbase1 : lbase0) + j + (j >= lab);
                    v[g][e] = __ldcs(logits + src);
                }
            }
        }
#pragma unroll
        for (int g = 0; g < GROUPS; g++) {
            if (ok[g]) {
                const int t0 = idx4[g] << 2;
                float4 o;
                o.x = SCALE * (v[g][0] - ((t0 + 0 >= b1) ? ft1 : ft0));
                o.y = SCALE * (v[g][1] - ((t0 + 1 >= b1) ? ft1 : ft0));
                o.z = SCALE * (v[g][2] - ((t0 + 2 >= b1) ? ft1 : ft0));
                o.w = SCALE * (v[g][3] - ((t0 + 3 >= b1) ? ft1 : ft0));
                __stcs(out4 + idx4[g], o);
            }
        }
    }

    // Epilogue scalars: block 0 computes all B rows' sines.
    if (blockIdx.x == 0) {
        const size_t sbase = (size_t)B * (size_t)Cm1;
        for (int r = threadIdx.x; r < B; r += TPB) {
            const int lab = i64 ? labels32[2 * r] : labels32[r];
            const float tg = __ldg(logits + (size_t)r * (size_t)C + lab);
            const float ftv = tg - MARGIN;
            // sin(acos(x)) == sqrt(1 - x^2) on [0,1)
            out[sbase + r]          = sqrtf(fmaxf(0.0f, 1.0f - tg * tg));
            out[sbase + B + r]      = sqrtf(fmaxf(0.0f, 1.0f - ftv * ftv));
            out[sbase + 2 * B + r]  = sinf(acosf(ftv) - acosf(tg));
        }
    }
}

extern "C" void kernel_launch(void* const* d_in, const int* in_sizes, int n_in,
                              void* d_out, int out_size) {
    const float* logits = (const float*)d_in[0];
    const int* labels32 = (const int*)d_in[1];
    float* out = (float*)d_out;

    const int B = in_sizes[1];              // 512
    const int C = in_sizes[0] / B;          // 100000

    const long long total = (long long)B * (C - 1);
    const int nblocks = (int)((total + TILE - 1) / TILE);   // 12500
    cosface_kernel<<<nblocks, TPB>>>(logits, labels32, out, B, C);
}